// round 17
// baseline (speedup 1.0000x reference)
#include <cuda_runtime.h>
#include <cuda_bf16.h>
#include <math.h>
#include <float.h>

#define XG 432
#define YG 496
#define CO 64
#define PMAX 64000
#define BMAX 4
#define HS 72   // bf16 stride per row (144 B): conflict-free fragment loads

typedef unsigned long long ull;

// Scratch (no allocations allowed anywhere)
__device__ ull          g_winner[BMAX * XG * YG];   // (epoch<<32)|(pil+1)
__device__ float        g_pooled[PMAX * CO];
__device__ unsigned int g_epoch;

// ---------------------------------------------------------------------------
// mma.sync m16n8k16 row.col f32 += bf16*bf16
// ---------------------------------------------------------------------------
__device__ __forceinline__ void mma_bf16(float d[4],
                                         unsigned a0, unsigned a1,
                                         unsigned a2, unsigned a3,
                                         unsigned b0, unsigned b1) {
    asm volatile(
        "mma.sync.aligned.m16n8k16.row.col.f32.bf16.bf16.f32 "
        "{%0,%1,%2,%3}, {%4,%5,%6,%7}, {%8,%9}, {%0,%1,%2,%3};"
        : "+f"(d[0]), "+f"(d[1]), "+f"(d[2]), "+f"(d[3])
        : "r"(a0), "r"(a1), "r"(a2), "r"(a3), "r"(b0), "r"(b1));
}

// ---------------------------------------------------------------------------
// Kernel 1: bump epoch (replaces full winner-map re-init; stale entries from
// previous launches carry an older epoch and are ignored by emit_k)
// ---------------------------------------------------------------------------
__global__ void epoch_k() { g_epoch = g_epoch + 1; }

// ---------------------------------------------------------------------------
// Kernel 2: PFN with split-bf16 tensor-core layer 2 + entry latency hoisting.
// 256 threads = 8 warps = 8 pillars per block; warp owns a pillar end-to-end.
// Winner scatter folded in (epoch-tagged 64-bit atomicMax, last-pillar-wins).
// Layer-1 feature broadcast via smem LDS.128 (replaces 6 shfls per point).
// ---------------------------------------------------------------------------
__global__ __launch_bounds__(256) void mlp_k(
    const float* __restrict__ pillars,
    const int*   __restrict__ coors,
    const int*   __restrict__ npoints,
    const float* __restrict__ W1, const float* __restrict__ g1,
    const float* __restrict__ b1, const float* __restrict__ m1,
    const float* __restrict__ v1,
    const float* __restrict__ W2, const float* __restrict__ g2,
    const float* __restrict__ b2, const float* __restrict__ m2,
    const float* __restrict__ v2, int P, int B)
{
    extern __shared__ char smem[];
    __nv_bfloat16* s_w2hi = (__nv_bfloat16*)smem;          // [64][HS]
    __nv_bfloat16* s_w2lo = s_w2hi + 64 * HS;              // [64][HS]
    __nv_bfloat16* s_h1hi = s_w2lo + 64 * HS;              // [8][32][HS]
    __nv_bfloat16* s_h1lo = s_h1hi + 8 * 32 * HS;          // [8][32][HS]
    float* s_s2   = (float*)(s_h1lo + 8 * 32 * HS);        // [64]
    float* s_t2   = s_s2 + 64;                             // [64]
    float* s_feat = s_t2 + 64;                             // [256][8] = 8KB

    const int tid  = threadIdx.x;
    const int w    = tid >> 5;
    const int lane = tid & 31;
    const int g    = lane >> 2;
    const int t4   = lane & 3;

    const int pil = blockIdx.x * 8 + w;
    const bool valid = (pil < P);

    // ============== ENTRY: issue ALL long-latency loads NOW ==============
    float4 pt = make_float4(0.f, 0.f, 0.f, 0.f);
    int cb = 0, cxi = 0, cyi = 0, npf = 1;
    if (valid) {
        pt  = *(const float4*)&pillars[(pil * 32 + lane) * 4];
        cb  = __ldg(&coors[4 * pil + 0]);
        cxi = __ldg(&coors[4 * pil + 1]);
        cyi = __ldg(&coors[4 * pil + 2]);
        npf = __ldg(&npoints[pil]);
    }
    // W1 / BN1 params for this lane's 2 channels (pillar-independent)
    const int c0 = 2 * lane, c1 = c0 + 1;
    const float s1a = g1[c0] / sqrtf(v1[c0] + 1e-5f);
    const float s1b = g1[c1] / sqrtf(v1[c1] + 1e-5f);
    const float t1a = b1[c0] - m1[c0] * s1a;
    const float t1b = b1[c1] - m1[c1] * s1b;
    float wa[6], wb[6];
    #pragma unroll
    for (int q = 0; q < 6; ++q) {
        wa[q] = W1[c0 * 6 + q] * s1a;
        wb[q] = W1[c1 * 6 + q] * s1b;
    }
    // BN2 params hoisted too (only tid<64 uses them)
    float s2v = 0.f, t2v = 0.f;
    if (tid < 64) {
        s2v = g2[tid] / sqrtf(v2[tid] + 1e-5f);
        t2v = b2[tid] - m2[tid] * s2v;
    }
    const unsigned int ep = g_epoch;

    // ---- winner scatter: epoch-tagged 64-bit atomicMax ----
    if (valid && lane == 0) {
        if ((unsigned)cb < (unsigned)B && (unsigned)cxi < XG &&
            (unsigned)cyi < YG) {
            ull tag = ((ull)ep << 32) | (ull)(pil + 1);
            atomicMax(&g_winner[(cb * XG + cxi) * YG + cyi], tag);
        }
    }

    // ---- stage W2 as bf16 hi/lo, vectorized LDG.128 (4 per thread) ----
    #pragma unroll
    for (int i = tid; i < 1024; i += 256) {
        int o = i >> 4, k4 = (i & 15) * 4;
        float4 wv = *(const float4*)&W2[o * 64 + k4];
        __nv_bfloat16* hid = &s_w2hi[o * HS + k4];
        __nv_bfloat16* lod = &s_w2lo[o * HS + k4];
        __nv_bfloat162 h01 = __floats2bfloat162_rn(wv.x, wv.y);
        __nv_bfloat162 h23 = __floats2bfloat162_rn(wv.z, wv.w);
        float2 f01 = __bfloat1622float2(h01);
        float2 f23 = __bfloat1622float2(h23);
        *(__nv_bfloat162*)(hid)     = h01;
        *(__nv_bfloat162*)(hid + 2) = h23;
        *(__nv_bfloat162*)(lod)     = __floats2bfloat162_rn(wv.x - f01.x,
                                                            wv.y - f01.y);
        *(__nv_bfloat162*)(lod + 2) = __floats2bfloat162_rn(wv.z - f23.x,
                                                            wv.w - f23.y);
    }
    if (tid < 64) {
        s_s2[tid] = s2v;
        s_t2[tid] = t2v;
    }
    __syncthreads();   // last block-wide sync

    __nv_bfloat16* h1hi = s_h1hi + w * 32 * HS;
    __nv_bfloat16* h1lo = s_h1lo + w * 32 * HS;

    if (valid) {
        // ---- features (lane = point); pillar data already in registers ----
        float sx = pt.x, sy = pt.y, sz = pt.z;
        #pragma unroll
        for (int off = 16; off > 0; off >>= 1) {
            sx += __shfl_xor_sync(0xffffffffu, sx, off);
            sy += __shfl_xor_sync(0xffffffffu, sy, off);
            sz += __shfl_xor_sync(0xffffffffu, sz, off);
        }
        const float fn  = (float)npf;
        const float cx = sx / fn, cy = sy / fn, cz = sz / fn;
        const float px = (float)cxi * 0.16f + 0.08f;
        const float py = (float)cyi * 0.16f - 39.6f;
        const float msk = (lane < npf) ? 1.0f : 0.0f;
        float f0 = pt.z * msk;
        float f1 = (pt.x - cx) * msk;
        float f2 = (pt.y - cy) * msk;
        float f3 = (pt.z - cz) * msk;
        float f4 = (pt.x - px) * msk;
        float f5 = (pt.y - py) * msk;

        // publish this point's features for warp-local broadcast reads
        float* frow = &s_feat[(w * 32 + lane) * 8];
        *(float4*)(frow)     = make_float4(f0, f1, f2, f3);
        *(float2*)(frow + 4) = make_float2(f4, f5);
    }
    __syncwarp();

    if (valid) {
        // ---- layer 1: per point p, this lane computes channels c0,c1.
        //      features read via conflict-free smem broadcast (2 LDS). ----
        const float* fbase = &s_feat[(w * 32) * 8];
        #pragma unroll 4
        for (int p = 0; p < 32; ++p) {
            float4 fa = *(const float4*)(fbase + p * 8);
            float2 fb = *(const float2*)(fbase + p * 8 + 4);
            float ha = t1a, hb = t1b;
            ha = fmaf(fa.x, wa[0], ha);  hb = fmaf(fa.x, wb[0], hb);
            ha = fmaf(fa.y, wa[1], ha);  hb = fmaf(fa.y, wb[1], hb);
            ha = fmaf(fa.z, wa[2], ha);  hb = fmaf(fa.z, wb[2], hb);
            ha = fmaf(fa.w, wa[3], ha);  hb = fmaf(fa.w, wb[3], hb);
            ha = fmaf(fb.x, wa[4], ha);  hb = fmaf(fb.x, wb[4], hb);
            ha = fmaf(fb.y, wa[5], ha);  hb = fmaf(fb.y, wb[5], hb);
            ha = fmaxf(ha, 0.0f);
            hb = fmaxf(hb, 0.0f);
            __nv_bfloat162 hi2 = __floats2bfloat162_rn(ha, hb);
            float2 hf = __bfloat1622float2(hi2);
            __nv_bfloat162 lo2 = __floats2bfloat162_rn(ha - hf.x, hb - hf.y);
            *(__nv_bfloat162*)&h1hi[p * HS + c0] = hi2;   // bank = lane, CF
            *(__nv_bfloat162*)&h1lo[p * HS + c0] = lo2;
        }
    }
    __syncwarp();

    // ---- layer 2: D[64 o][32 pt] via 4 mtiles x 4 ntiles x 4 ktiles ----
    float d[4][4][4];
    #pragma unroll
    for (int m = 0; m < 4; ++m)
        #pragma unroll
        for (int n = 0; n < 4; ++n)
            #pragma unroll
            for (int r = 0; r < 4; ++r) d[m][n][r] = 0.0f;

    #pragma unroll
    for (int kt = 0; kt < 4; ++kt) {
        const int kA = kt * 16 + 2 * t4;
        const int kB = kA + 8;

        unsigned ahi[4][4];
        #pragma unroll
        for (int m = 0; m < 4; ++m) {
            int r0 = (16 * m + g) * HS, r1 = r0 + 8 * HS;
            ahi[m][0] = *(const unsigned*)&s_w2hi[r0 + kA];
            ahi[m][1] = *(const unsigned*)&s_w2hi[r1 + kA];
            ahi[m][2] = *(const unsigned*)&s_w2hi[r0 + kB];
            ahi[m][3] = *(const unsigned*)&s_w2hi[r1 + kB];
        }
        unsigned bhi[4][2], blo[4][2];
        #pragma unroll
        for (int n = 0; n < 4; ++n) {
            int pr = (8 * n + g) * HS;
            bhi[n][0] = *(const unsigned*)&h1hi[pr + kA];
            bhi[n][1] = *(const unsigned*)&h1hi[pr + kB];
            blo[n][0] = *(const unsigned*)&h1lo[pr + kA];
            blo[n][1] = *(const unsigned*)&h1lo[pr + kB];
        }
        // hi*hi and hi*lo passes
        #pragma unroll
        for (int m = 0; m < 4; ++m)
            #pragma unroll
            for (int n = 0; n < 4; ++n) {
                mma_bf16(d[m][n], ahi[m][0], ahi[m][1], ahi[m][2], ahi[m][3],
                         bhi[n][0], bhi[n][1]);
                mma_bf16(d[m][n], ahi[m][0], ahi[m][1], ahi[m][2], ahi[m][3],
                         blo[n][0], blo[n][1]);
            }
        // lo*hi pass
        unsigned alo[4][4];
        #pragma unroll
        for (int m = 0; m < 4; ++m) {
            int r0 = (16 * m + g) * HS, r1 = r0 + 8 * HS;
            alo[m][0] = *(const unsigned*)&s_w2lo[r0 + kA];
            alo[m][1] = *(const unsigned*)&s_w2lo[r1 + kA];
            alo[m][2] = *(const unsigned*)&s_w2lo[r0 + kB];
            alo[m][3] = *(const unsigned*)&s_w2lo[r1 + kB];
        }
        #pragma unroll
        for (int m = 0; m < 4; ++m)
            #pragma unroll
            for (int n = 0; n < 4; ++n)
                mma_bf16(d[m][n], alo[m][0], alo[m][1], alo[m][2], alo[m][3],
                         bhi[n][0], bhi[n][1]);
    }

    // ---- epilogue: BN2 (sign-safe via max&min), max over points ----
    #pragma unroll
    for (int m = 0; m < 4; ++m) {
        float mxA = -FLT_MAX, mnA = FLT_MAX;   // row o = 16m + g
        float mxB = -FLT_MAX, mnB = FLT_MAX;   // row o = 16m + g + 8
        #pragma unroll
        for (int n = 0; n < 4; ++n) {
            mxA = fmaxf(mxA, fmaxf(d[m][n][0], d[m][n][1]));
            mnA = fminf(mnA, fminf(d[m][n][0], d[m][n][1]));
            mxB = fmaxf(mxB, fmaxf(d[m][n][2], d[m][n][3]));
            mnB = fminf(mnB, fminf(d[m][n][2], d[m][n][3]));
        }
        #pragma unroll
        for (int off = 1; off <= 2; off <<= 1) {
            mxA = fmaxf(mxA, __shfl_xor_sync(0xffffffffu, mxA, off));
            mnA = fminf(mnA, __shfl_xor_sync(0xffffffffu, mnA, off));
            mxB = fmaxf(mxB, __shfl_xor_sync(0xffffffffu, mxB, off));
            mnB = fminf(mnB, __shfl_xor_sync(0xffffffffu, mnB, off));
        }
        if (t4 == 0 && valid) {
            int oA = 16 * m + g, oB = oA + 8;
            float sA = s_s2[oA], sB = s_s2[oB];
            float vA = (sA >= 0.0f) ? fmaf(sA, mxA, s_t2[oA])
                                    : fmaf(sA, mnA, s_t2[oA]);
            float vB = (sB >= 0.0f) ? fmaf(sB, mxB, s_t2[oB])
                                    : fmaf(sB, mnB, s_t2[oB]);
            g_pooled[pil * 64 + oA] = vA;
            g_pooled[pil * 64 + oB] = vB;
        }
    }
}

// ---------------------------------------------------------------------------
// Kernel 3: emit pseudo-image (B, C, Y, X). grid = (YG, 4*B), 128 threads.
// Winner entries valid only if their epoch tag matches the current epoch.
// ---------------------------------------------------------------------------
__global__ __launch_bounds__(128) void emit_k(float* __restrict__ out) {
    __shared__ ull s_wi[XG];
    const int y    = blockIdx.x;
    const int b    = blockIdx.y >> 2;
    const int part = blockIdx.y & 3;
    const unsigned int ep = g_epoch;
    for (int x = threadIdx.x; x < XG; x += 128)
        s_wi[x] = g_winner[(b * XG + x) * YG + y];
    __syncthreads();

    const int t = threadIdx.x;
    if (t >= XG / 4) return;   // 108 active threads
    const int x0 = t * 4;

    const float* pp[4];
    bool ok[4];
    #pragma unroll
    for (int i = 0; i < 4; ++i) {
        ull e = s_wi[x0 + i];
        ok[i] = ((unsigned int)(e >> 32) == ep);
        int wi = ok[i] ? ((int)(unsigned int)e - 1) : 0;
        pp[i] = g_pooled + wi * 64;
    }

    const float4 z4 = make_float4(0.f, 0.f, 0.f, 0.f);
    const long long cstride = (long long)YG * XG;
    float* op = out + ((long long)b * CO + part * 16) * cstride
                    + (long long)y * XG + x0;

    #pragma unroll
    for (int cq = part * 4; cq < part * 4 + 4; ++cq) {
        float4 v[4];
        #pragma unroll
        for (int i = 0; i < 4; ++i)
            v[i] = ok[i] ? *(const float4*)(pp[i] + cq * 4) : z4;
        *(float4*)op = make_float4(v[0].x, v[1].x, v[2].x, v[3].x); op += cstride;
        *(float4*)op = make_float4(v[0].y, v[1].y, v[2].y, v[3].y); op += cstride;
        *(float4*)op = make_float4(v[0].z, v[1].z, v[2].z, v[3].z); op += cstride;
        *(float4*)op = make_float4(v[0].w, v[1].w, v[2].w, v[3].w); op += cstride;
    }
}

// ---------------------------------------------------------------------------
// kernel_launch — graph-capturable, allocation-free
// ---------------------------------------------------------------------------
extern "C" void kernel_launch(void* const* d_in, const int* in_sizes, int n_in,
                              void* d_out, int out_size) {
    const float* pillars = (const float*)d_in[0];
    const int*   coors   = (const int*)d_in[1];
    const int*   npts    = (const int*)d_in[2];

    int wbase = (in_sizes[3] == 384) ? 3 : 4;  // skip batch_size slot if present
    const float* W1 = (const float*)d_in[wbase + 0];
    const float* g1 = (const float*)d_in[wbase + 1];
    const float* b1 = (const float*)d_in[wbase + 2];
    const float* m1 = (const float*)d_in[wbase + 3];
    const float* v1 = (const float*)d_in[wbase + 4];
    const float* W2 = (const float*)d_in[wbase + 5];
    const float* g2 = (const float*)d_in[wbase + 6];
    const float* b2 = (const float*)d_in[wbase + 7];
    const float* m2 = (const float*)d_in[wbase + 8];
    const float* v2 = (const float*)d_in[wbase + 9];

    int P = in_sizes[0] / (32 * 4);
    int B = out_size / (CO * XG * YG);
    if (B > BMAX) B = BMAX;
    if (P > PMAX) P = PMAX;

    // smem: W2 hi/lo + h1 hi/lo (bf16) + s2/t2 (fp32) + feat (256*8 fp32)
    const int smemBytes = (2 * 64 * HS + 2 * 8 * 32 * HS) * 2 + 2 * 64 * 4
                          + 256 * 8 * 4;
    cudaFuncSetAttribute(mlp_k, cudaFuncAttributeMaxDynamicSharedMemorySize,
                         smemBytes);

    epoch_k<<<1, 1>>>();
    mlp_k<<<(P + 7) / 8, 256, smemBytes>>>(pillars, coors, npts,
                                           W1, g1, b1, m1, v1,
                                           W2, g2, b2, m2, v2, P, B);
    emit_k<<<dim3(YG, 4 * B), 128>>>((float*)d_out);
}